// round 14
// baseline (speedup 1.0000x reference)
#include <cuda_runtime.h>

// predictor_interp2d: nearest-neighbor gather from N=1024 points onto a 256x256 grid.
// d_in[0] = R_pc  [B=2, C=4, N=1024] float32
// d_in[1] = XY_pc [B=2, 2, N=1024]   float32
// d_out   = R_grd [B=2, C=4, 256, 256] float32
//
// Locked R9 structure + two cuts:
//  - binning rank comes from the FIRST atomicAdd (no second atomic pass/scur),
//  - search scans the clipped 3x3 first (radius-1 certified), bound-checks,
//    and only failing warps enter the expanding-ring loop from r=2.
//
// One 1024-thread block per 32x32-cell region (128 blocks, one wave); block
// bins all 1024 batch points into a 32x32 smem CSR (1 pt/thread), stages R in
// smem. Argmin key = (ordered_uint(d2) << 32) | point_index, u64 min ==
// (min d2, then min index) == jnp.argmin first-min semantics. d2 uses the
// EXACT reference arithmetic (bit-matched since R2) -> bit-identical output,
// scatter order irrelevant.

#define NPTS  1024
#define NB    32
#define BINW  0.03125f

__global__ __launch_bounds__(1024, 1)
void nn_fused(const float* __restrict__ XY,
              const float* __restrict__ R,
              float* __restrict__ out) {
    __shared__ float4 spts[NPTS];        // {px, py, s, index-as-bits}, bin-ordered
    __shared__ int    soff[NB*NB + 1];   // CSR offsets (1025 ints)
    __shared__ int    scnt[NB*NB];       // bin counts (atomic rank source)
    __shared__ int    swsum[32];         // per-warp scan partials
    __shared__ float  sR[4 * NPTS];      // staged field values (16 KB)

    const int t    = threadIdx.x;
    const int b    = blockIdx.x >> 6;            // 64 regions per batch
    const int quad = blockIdx.x & 63;            // 8x8 regions of 32x32 cells

    // ---- Phase 1: block-local binning of all 1024 points (1 per thread) ----
    const float* xy = XY + b * (2 * NPTS);
    const float* Rb = R  + b * (4 * NPTS);

    scnt[t] = 0;

    // Stage R to smem (coalesced; latency overlapped with binning below).
    #pragma unroll
    for (int c = 0; c < 4; ++c)
        sR[c * NPTS + t] = Rb[c * NPTS + t];

    __syncthreads();

    const float x = xy[t];
    const float y = xy[NPTS + t];
    const int bxx = min(max((int)(x * 32.0f), 0), NB - 1);
    const int byy = min(max((int)(y * 32.0f), 0), NB - 1);
    const int pbin = byy * NB + bxx;
    const int rank = atomicAdd(&scnt[pbin], 1);  // within-bin rank (order-free)
    __syncthreads();

    // 1024-wide exclusive scan: warp shfl scan + 32-partial warp-0 scan.
    {
        const int v = scnt[t];
        int incl = v;
        #pragma unroll
        for (int d = 1; d < 32; d <<= 1) {
            const int n = __shfl_up_sync(0xffffffffu, incl, d);
            if ((t & 31) >= d) incl += n;
        }
        if ((t & 31) == 31) swsum[t >> 5] = incl;
        __syncthreads();
        if (t < 32) {
            const int w = swsum[t];
            int iw = w;
            #pragma unroll
            for (int d = 1; d < 32; d <<= 1) {
                const int n = __shfl_up_sync(0xffffffffu, iw, d);
                if (t >= d) iw += n;
            }
            swsum[t] = iw - w;                   // exclusive warp base
        }
        __syncthreads();
        soff[t] = incl - v + swsum[t >> 5];      // exclusive prefix for bin t
        if (t == 0) soff[NB*NB] = NPTS;
    }
    __syncthreads();

    {
        const int pos = soff[pbin] + rank;       // no second atomic needed
        // s with the reference's rounding order (mul, mul, add)
        const float s = __fadd_rn(__fmul_rn(x, x), __fmul_rn(y, y));
        spts[pos] = make_float4(x, y, s, __int_as_float(t));
    }
    __syncthreads();

    // ---- Phase 2: NN search ----
    // Thread u (0..255) within tile sel (0..3); each warp = 2 cell-rows of one
    // 16x16 tile -> home bin row warp-uniform.
    const int sel = t >> 8;
    const int u   = t & 255;
    const int qx  = quad & 7, qy = quad >> 3;
    const int cx  = qx * 32 + (sel & 1) * 16 + (u & 15);
    const int cy  = qy * 32 + (sel >> 1) * 16 + (u >> 4);
    const int cell = cy * 256 + cx;
    const int bx  = cx >> 3;                     // 8 cells per 1/32 bin
    const int by  = cy >> 3;

    const float inv = 1.0f / 256.0f;
    const float gx = ((float)cx + 0.5f) * inv;
    const float gy = ((float)cy + 0.5f) * inv;
    const float g2 = gx * gx + gy * gy;          // geometry bound only

    // Packed (ordered d2, index) key; u64 min == lexicographic first-min.
    unsigned long long bestk = 0xFFFFFFFFFFFFFFFFull;

    #define SCAN_RANGE(E0, E1)                                                  \
        _Pragma("unroll 2")                                                     \
        for (int k = (E0); k < (E1); ++k) {                                     \
            const float4 p = spts[k];                                           \
            const float dot = __fmaf_rn(p.y, gy, __fmul_rn(p.x, gx));           \
            const float d   = __fmaf_rn(-2.0f, dot, p.z);                       \
            unsigned int ub = __float_as_uint(d);                               \
            ub ^= (unsigned int)(((int)ub >> 31)) | 0x80000000u;                \
            const unsigned long long key =                                      \
                ((unsigned long long)ub << 32) | __float_as_uint(p.w);          \
            bestk = min(bestk, key);                                            \
        }

    // Fast path: clipped 3x3 bin neighborhood == scanned square radius 1.
    // Rows are CSR-contiguous -> <=3 flat segments. P(NN inside) ~0.96-0.999.
    {
        const int xx0 = max(bx - 1, 0), xx1 = min(bx + 1, NB - 1);
        const int yy0 = max(by - 1, 0), yy1 = min(by + 1, NB - 1);
        for (int yb = yy0; yb <= yy1; ++yb) {
            const int e0 = soff[yb * NB + xx0];
            const int e1 = soff[yb * NB + xx1 + 1];
            SCAN_RANGE(e0, e1)
        }
    }

    // Checked expansion: rings r>=2 with rounding-safe termination. The r=2
    // bound is exactly the radius-1 certificate of the 3x3 scan above; ~50%
    // of warps exit before ring r=2.
    for (int r = 2; r < NB; ++r) {
        // Decode current best d2 (NaN if nothing scanned yet -> keep going).
        const unsigned int ob = (unsigned int)(bestk >> 32);
        const unsigned int fb = (ob & 0x80000000u) ? (ob ^ 0x80000000u) : ~ob;
        const float best = __uint_as_float(fb);
        // Distance to boundary of scanned square [bx-(r-1), bx+(r-1)]^2;
        // domain-edge faces excluded. Unscanned points have computed
        // d2 >= f^2 - g2 - eps; slack 1e-4 >> eps forbids beating OR tying,
        // so extra rings scanned for warp-mates can't change this thread.
        const float fL = (bx - (r - 1) >= 1)      ? (gx - (float)(bx - (r - 1)) * BINW) : 1e30f;
        const float fR = (bx + (r - 1) <= NB - 2) ? ((float)(bx + r) * BINW - gx)       : 1e30f;
        const float fB = (by - (r - 1) >= 1)      ? (gy - (float)(by - (r - 1)) * BINW) : 1e30f;
        const float fT = (by + (r - 1) <= NB - 2) ? ((float)(by + r) * BINW - gy)       : 1e30f;
        const float f  = fminf(fminf(fL, fR), fminf(fB, fT));
        const int cont = !(f * f > best + g2 + 1e-4f);       // NaN best -> cont
        if (!__any_sync(0xffffffffu, cont)) break;           // per-warp exit

        const int x0 = max(bx - r, 0), x1 = min(bx + r, NB - 1);
        const int y0 = max(by - r, 0), y1 = min(by + r, NB - 1);
        for (int yb = y0; yb <= y1; ++yb) {
            if (yb == by - r || yb == by + r) {
                const int e0 = soff[yb * NB + x0];
                const int e1 = soff[yb * NB + x1 + 1];
                SCAN_RANGE(e0, e1)
            } else {
                if (bx - r >= 0) {
                    const int bb = yb * NB + (bx - r);
                    SCAN_RANGE(soff[bb], soff[bb + 1])
                }
                if (bx + r <= NB - 1) {
                    const int bb = yb * NB + (bx + r);
                    SCAN_RANGE(soff[bb], soff[bb + 1])
                }
            }
        }
    }
    #undef SCAN_RANGE

    const int bi = (int)(bestk & 0xFFFFFFFFull);

    // ---- Phase 3: gather 4 channels from smem-staged R ----
    float* ob = out + b * (4 * 65536);
    #pragma unroll
    for (int c = 0; c < 4; ++c)
        ob[c * 65536 + cell] = sR[c * NPTS + bi];
}

extern "C" void kernel_launch(void* const* d_in, const int* in_sizes, int n_in,
                              void* d_out, int out_size) {
    const float* R  = (const float*)d_in[0];   // [2,4,1024]
    const float* XY = (const float*)d_in[1];   // [2,2,1024]
    float* out = (float*)d_out;                // [2,4,256,256]

    nn_fused<<<128, 1024>>>(XY, R, out);
}